// round 16
// baseline (speedup 1.0000x reference)
#include <cuda_runtime.h>
#include <cstdint>
#include <cstddef>

// TensorFusion: B=32, N=4096, C=16, D=256
//   out[b,c,d]  = (1/N) * sum_n [r[b,n,c] >= 0.5] * v[b,n,d]        c in 0..15
//   out[b,16,d] = (1/N) * sum_n [all c: r[b,n,c] < 0.5] * v[b,n,d]

#define B_DIM 32
#define N_DIM 4096
#define C_DIM 16
#define D_DIM 256
#define OUT_C (C_DIM + 1)

#define GRID_X 16                  // chunk-pairs per batch -> 512 CTAs total
#define TILES 2                    // tiles per CTA (same output block)
#define NCHUNK 128                 // rows per tile
#define THREADS 256
#define MF_PAD 20                  // floats per mask row (80B, 16B-aligned)

#define S_STAGES 3                 // cp.async ring depth (2 stages in flight)
#define RSTAGE 8                   // rows per stage
#define STAGE_ITERS (NCHUNK / RSTAGE)      // 16
#define STAGE_BYTES (RSTAGE * D_DIM * 4)   // 8192 (flat contiguous rows)
#define MASK_BYTES (NCHUNK * MF_PAD * 4)   // 10240
#define RING_BYTES (S_STAGES * STAGE_BYTES)// 24576
#define SMEM_TOTAL (MASK_BYTES + RING_BYTES) // 34816

__global__ void tf_zero_kernel(float* __restrict__ out, int n) {
    int i = blockIdx.x * blockDim.x + threadIdx.x;
    if (i < n) out[i] = 0.0f;
}

// Packed f32x2 FMA: acc.{lo,hi} += m.{lo,hi} * v.{lo,hi}  (one FFMA2, fma pipe)
#define FMA2(acc, m, vv) \
    asm("fma.rn.f32x2 %0, %1, %2, %0;" : "+l"(acc) : "l"(m), "l"(vv))
// Duplicate a float into both f32x2 lanes.
#define DUP2(dst, f) \
    asm("mov.b64 %0, {%1, %1};" : "=l"(dst) : "f"(f))

__device__ __forceinline__ void cp_async16(uint32_t dst_smem, const void* src) {
    asm volatile("cp.async.cg.shared.global [%0], [%1], 16;"
                 :: "r"(dst_smem), "l"(src));
}
#define CP_COMMIT() asm volatile("cp.async.commit_group;" ::: "memory")
#define CP_WAIT2()  asm volatile("cp.async.wait_group 2;" ::: "memory")

extern __shared__ __align__(16) char dynsmem[];

__global__ __launch_bounds__(THREADS, 4)
void tf_fusion_kernel(const float* __restrict__ r,
                      const float* __restrict__ v,
                      float* __restrict__ out) {
    // Layout: [maskf: NCHUNK x MF_PAD floats][ring: 3 x 8KB stages]
    float* maskf = reinterpret_cast<float*>(dynsmem);
    char*  pool  = dynsmem + MASK_BYTES;

    const int b  = blockIdx.y;
    const int t  = threadIdx.x;
    const int dp = t & 127;        // d-pair: owns d = 2*dp, 2*dp+1
    const int ch = t >> 7;         // channel half: 0 -> c0..7, 1 -> c8..16

    uint32_t pool_u32;
    asm("{ .reg .u64 tt; cvta.to.shared.u64 tt, %1; cvt.u32.u64 %0, tt; }"
        : "=r"(pool_u32) : "l"(pool));
    // Stage copy slots: flat 8KB per stage; thread copies 2 x 16B.
    const uint32_t sd0 = pool_u32 + (uint32_t)(t * 16);
    const uint32_t sd1 = pool_u32 + (uint32_t)(4096 + t * 16);

    // Accumulators: 4 channel-pairs x 2 d + special (ch=1 only), f32x2 lanes
    // = (c_even, c_odd).  20 registers total.
    unsigned long long accp[4][2];
    unsigned long long accs[2];
    #pragma unroll
    for (int p = 0; p < 4; ++p) { accp[p][0] = 0ull; accp[p][1] = 0ull; }
    accs[0] = 0ull; accs[1] = 0ull;

    #define ISSUE_STAGE(s)                                                     \
    do {                                                                       \
        uint32_t _so = (uint32_t)(((s) % S_STAGES) * STAGE_BYTES);             \
        const float* _g = gvt + (size_t)(s) * (RSTAGE * D_DIM);                \
        cp_async16(sd0 + _so, _g + t * 4);                                     \
        cp_async16(sd1 + _so, _g + 1024 + t * 4);                              \
        CP_COMMIT();                                                           \
    } while (0)

    #pragma unroll 1
    for (int tile = 0; tile < TILES; ++tile) {
        const int n0 = (blockIdx.x * TILES + tile) * NCHUNK;

        // ---- Phase A: 17 mask floats (0.0/1.0) per row (threads 0..127) ----
        if (t < NCHUNK) {
            const float4* rp = reinterpret_cast<const float4*>(
                r + (size_t)(b * N_DIM + n0 + t) * C_DIM);
            unsigned m = 0u;
            #pragma unroll
            for (int j = 0; j < 4; ++j) {
                float4 x = rp[j];
                m |= (x.x >= 0.5f ? 1u : 0u) << (4 * j + 0);
                m |= (x.y >= 0.5f ? 1u : 0u) << (4 * j + 1);
                m |= (x.z >= 0.5f ? 1u : 0u) << (4 * j + 2);
                m |= (x.w >= 0.5f ? 1u : 0u) << (4 * j + 3);
            }
            if (m == 0u) m = 1u << 16;   // special: no category matched
            #pragma unroll
            for (int c = 0; c < OUT_C; ++c) {
                maskf[t * MF_PAD + c] = (float)((m >> c) & 1u);
            }
        }

        const float* gvt = v + (size_t)(b * N_DIM + n0) * D_DIM;
        // Prologue: stages 0 and 1 in flight (ring fully drained last tile).
        ISSUE_STAGE(0);
        ISSUE_STAGE(1);
        __syncthreads();   // masks ready + everyone past prologue

        #pragma unroll 1
        for (int i = 0; i < STAGE_ITERS; ++i) {
            if (i + 2 < STAGE_ITERS) ISSUE_STAGE(i + 2);
            else                     CP_COMMIT();   // keep group count moving
            CP_WAIT2();                  // own copies of stage i complete
            __syncthreads();             // everyone's copies complete

            const char*  vsb  = pool + (i % S_STAGES) * STAGE_BYTES + dp * 8;
            const float* mrow = maskf + (size_t)(i * RSTAGE) * MF_PAD;
            #pragma unroll
            for (int rr = 0; rr < RSTAGE; ++rr) {
                float2 vv = *reinterpret_cast<const float2*>(vsb + rr * 1024);
                unsigned long long vd0, vd1;
                DUP2(vd0, vv.x);
                DUP2(vd1, vv.y);
                const float* mr = mrow + rr * MF_PAD;
                // 2 broadcast LDS.128: 4 channel-pairs for this half.
                ulonglong2 mA = *reinterpret_cast<const ulonglong2*>(mr + ch * 8);
                ulonglong2 mB = *reinterpret_cast<const ulonglong2*>(mr + ch * 8 + 4);
                FMA2(accp[0][0], mA.x, vd0); FMA2(accp[0][1], mA.x, vd1);
                FMA2(accp[1][0], mA.y, vd0); FMA2(accp[1][1], mA.y, vd1);
                FMA2(accp[2][0], mB.x, vd0); FMA2(accp[2][1], mB.x, vd1);
                FMA2(accp[3][0], mB.y, vd0); FMA2(accp[3][1], mB.y, vd1);
                if (ch) {
                    unsigned long long ms;
                    DUP2(ms, mr[16]);
                    FMA2(accs[0], ms, vd0);
                    FMA2(accs[1], ms, vd1);
                }
            }
            __syncthreads();             // all consumers done before slot reuse
        }
        // loop-end barrier also orders next tile's mask rewrite
    }

    // ---- Final: scale + atomic reduction (thread owns its (c-half, d-pair)) ----
    const float scale = 1.0f / (float)N_DIM;
    float* op = out + (size_t)b * OUT_C * D_DIM + dp * 2;
    const int c0 = ch * 8;
    #pragma unroll
    for (int p = 0; p < 4; ++p) {
        #pragma unroll
        for (int d = 0; d < 2; ++d) {
            float2 f = *reinterpret_cast<const float2*>(&accp[p][d]);
            atomicAdd(op + (c0 + 2 * p + 0) * D_DIM + d, f.x * scale);
            atomicAdd(op + (c0 + 2 * p + 1) * D_DIM + d, f.y * scale);
        }
    }
    if (ch) {
        #pragma unroll
        for (int d = 0; d < 2; ++d) {
            float2 f = *reinterpret_cast<const float2*>(&accs[d]);
            atomicAdd(op + 16 * D_DIM + d, f.x * scale);
        }
    }
}

extern "C" void kernel_launch(void* const* d_in, const int* in_sizes, int n_in,
                              void* d_out, int out_size) {
    // Inputs per metadata order: r_tensor (B*N*C), v_tensor (B*N*D).
    // Disambiguate defensively by element count.
    const float* r = (const float*)d_in[0];
    const float* v = (const float*)d_in[1];
    if (n_in >= 2 && in_sizes[0] == B_DIM * N_DIM * D_DIM &&
        in_sizes[1] == B_DIM * N_DIM * C_DIM) {
        r = (const float*)d_in[1];
        v = (const float*)d_in[0];
    }
    float* out = (float*)d_out;

    // Host-side attribute set (not a stream op; graph-capture safe, idempotent).
    cudaFuncSetAttribute(tf_fusion_kernel,
                         cudaFuncAttributeMaxDynamicSharedMemorySize, SMEM_TOTAL);

    const int out_elems = B_DIM * OUT_C * D_DIM;  // 139264
    tf_zero_kernel<<<(out_elems + 255) / 256, 256>>>(out, out_elems);

    dim3 grid(GRID_X, B_DIM);   // 512 CTAs = one full wave at occ >= 4
    tf_fusion_kernel<<<grid, THREADS, SMEM_TOTAL>>>(r, v, out);
}